// round 9
// baseline (speedup 1.0000x reference)
#include <cuda_runtime.h>
#include <math.h>
#include <stdint.h>
#include <cuda_fp16.h>

#define L_ 256
#define C_ 128
#define G_ 4
#define P_ 32
#define R_ (L_*L_)   // 65536 rows

// Scratch (allocation-free: device globals)
static __device__ float d_q [R_*C_];
static __device__ float d_k [R_*C_];
static __device__ float d_v [R_*C_];
static __device__ float d_gt[R_*C_];
static __device__ float d_o [R_*C_];
static __device__ float d_bT[(size_t)G_*R_];   // bias transposed: [g][k][j]
static __device__ float d_WT [512*128];        // fused [Wq*qs|Wk|Wv|Wg]^T  [n][k], tf32-rounded
static __device__ float d_WoT[128*128];        // Wo^T [n][k], tf32-rounded

__device__ __forceinline__ float sigmoidf_(float x){ return 1.f/(1.f+__expf(-x)); }

__device__ __forceinline__ float f2tf32(float f){
    uint32_t r; asm("cvt.rna.tf32.f32 %0, %1;" : "=r"(r) : "f"(f));
    return __uint_as_float(r);
}
__device__ __forceinline__ void mma_tf32(float* d, const uint32_t* a, const uint32_t* b){
    asm volatile("mma.sync.aligned.m16n8k8.row.col.f32.tf32.tf32.f32 "
        "{%0,%1,%2,%3}, {%4,%5,%6,%7}, {%8,%9}, {%0,%1,%2,%3};"
        : "+f"(d[0]),"+f"(d[1]),"+f"(d[2]),"+f"(d[3])
        : "r"(a[0]),"r"(a[1]),"r"(a[2]),"r"(a[3]), "r"(b[0]),"r"(b[1]));
}

#define PAD 68   // floats per smem row for the dense GEMMs

// ---------------------------------------------------------------------------
// Prep: transpose weights into [n][k], tf32-round, fold 1/sqrt(P) into WqT.
// ---------------------------------------------------------------------------
__global__ void prep_kernel(const float* __restrict__ Wq, const float* __restrict__ Wk,
                            const float* __restrict__ Wv, const float* __restrict__ Wg,
                            const float* __restrict__ Wo)
{
    int n = blockIdx.x, k = threadIdx.x;
    if (n < 512){
        int m = n>>7, c = n&127;
        const float* W = (m==0)?Wq:(m==1)?Wk:(m==2)?Wv:Wg;
        float w = W[k*C_ + c];
        if (m==0) w *= 0.17677669529663687f;   // 1/sqrt(32)
        d_WT[n*C_ + k] = f2tf32(w);
    } else {
        int c = n - 512;
        d_WoT[c*C_ + k] = f2tf32(Wo[k*C_ + c]);
    }
}

// ---------------------------------------------------------------------------
// Bias: d_bT[g][k][j] = x[j*L+k,:] . Wb[:,g]   (fp32, tiny)
// ---------------------------------------------------------------------------
__global__ void __launch_bounds__(256) bias_kernel(const float* __restrict__ x,
                                                   const float* __restrict__ Wb)
{
    __shared__ float4 sWb[128];   // [c] -> (g0..g3)
    int tid = threadIdx.x;
    if (tid < 128)
        sWb[tid] = make_float4(Wb[tid*4+0], Wb[tid*4+1], Wb[tid*4+2], Wb[tid*4+3]);
    __syncthreads();
    int r = blockIdx.x*256 + tid;
    const float4* xr = (const float4*)(x + (size_t)r*C_);
    float a0=0.f,a1=0.f,a2=0.f,a3=0.f;
    #pragma unroll 8
    for (int c4=0;c4<32;c4++){
        float4 xv = xr[c4];
        float4 w0 = sWb[c4*4+0], w1 = sWb[c4*4+1], w2 = sWb[c4*4+2], w3 = sWb[c4*4+3];
        a0 = fmaf(xv.x,w0.x,a0); a1 = fmaf(xv.x,w0.y,a1); a2 = fmaf(xv.x,w0.z,a2); a3 = fmaf(xv.x,w0.w,a3);
        a0 = fmaf(xv.y,w1.x,a0); a1 = fmaf(xv.y,w1.y,a1); a2 = fmaf(xv.y,w1.z,a2); a3 = fmaf(xv.y,w1.w,a3);
        a0 = fmaf(xv.z,w2.x,a0); a1 = fmaf(xv.z,w2.y,a1); a2 = fmaf(xv.z,w2.z,a2); a3 = fmaf(xv.z,w2.w,a3);
        a0 = fmaf(xv.w,w3.x,a0); a1 = fmaf(xv.w,w3.y,a1); a2 = fmaf(xv.w,w3.z,a2); a3 = fmaf(xv.w,w3.w,a3);
    }
    int kk = r & (L_-1), jj = r >> 8;
    d_bT[(size_t)0*R_ + kk*L_ + jj] = a0;
    d_bT[(size_t)1*R_ + kk*L_ + jj] = a1;
    d_bT[(size_t)2*R_ + kk*L_ + jj] = a2;
    d_bT[(size_t)3*R_ + kk*L_ + jj] = a3;
}

// ---------------------------------------------------------------------------
// Proj via mma.sync tf32. CTA: 128 rows x 128 cols. Grid (512, 4).
// ---------------------------------------------------------------------------
#define GEMM_SMEM (2*128*PAD*4)

__global__ void __launch_bounds__(256,2) proj_kernel(
    const float* __restrict__ x, const float* __restrict__ bg)
{
    extern __shared__ float sm[];
    float* sA = sm;
    float* sB = sm + 128*PAD;

    const int tid = threadIdx.x, wid = tid>>5, lane = tid&31;
    const int warp_m = wid & 3, warp_n = wid >> 2;
    const int rbase = blockIdx.x * 128;
    const int mat   = blockIdx.y;
    const int cbase = mat * 128;

    float acc[2][8][4];
    #pragma unroll
    for (int mt=0;mt<2;mt++)
        #pragma unroll
        for (int nt=0;nt<8;nt++)
            #pragma unroll
            for (int e=0;e<4;e++) acc[mt][nt][e]=0.f;

    const int g4 = lane>>2, t4 = lane&3;

    for (int kc=0; kc<2; kc++){
        #pragma unroll 4
        for (int i=tid; i<2048; i+=256){
            int row = i>>4, k4 = i&15;
            float4 v = ((const float4*)x)[(size_t)(rbase+row)*32 + kc*16 + k4];
            float* d = sA + row*PAD + k4*4;
            d[0]=f2tf32(v.x); d[1]=f2tf32(v.y); d[2]=f2tf32(v.z); d[3]=f2tf32(v.w);
        }
        #pragma unroll 4
        for (int i=tid; i<2048; i+=256){
            int col = i>>4, k4 = i&15;
            float4 v = ((const float4*)d_WT)[(size_t)(cbase+col)*32 + kc*16 + k4];
            *(float4*)(sB + col*PAD + k4*4) = v;
        }
        __syncthreads();

        #pragma unroll
        for (int k8=0;k8<8;k8++){
            const int k0 = k8*8;
            uint32_t a[2][4];
            #pragma unroll
            for (int mt=0;mt<2;mt++){
                const float* pa = sA + (warp_m*32 + mt*16 + g4)*PAD + k0 + t4;
                a[mt][0]=__float_as_uint(pa[0]);
                a[mt][1]=__float_as_uint(pa[8*PAD]);
                a[mt][2]=__float_as_uint(pa[4]);
                a[mt][3]=__float_as_uint(pa[8*PAD+4]);
            }
            #pragma unroll
            for (int nt=0;nt<8;nt++){
                const float* pb = sB + (warp_n*64 + nt*8 + g4)*PAD + k0 + t4;
                uint32_t b[2];
                b[0]=__float_as_uint(pb[0]);
                b[1]=__float_as_uint(pb[4]);
                mma_tf32(acc[0][nt], a[0], b);
                mma_tf32(acc[1][nt], a[1], b);
            }
        }
        __syncthreads();
    }

    float* dst = (mat==0)?d_q:(mat==1)?d_k:(mat==2)?d_v:d_gt;
    #pragma unroll
    for (int mt=0;mt<2;mt++){
        #pragma unroll
        for (int half=0;half<2;half++){
            const int row = rbase + warp_m*32 + mt*16 + g4 + half*8;
            #pragma unroll
            for (int nt=0;nt<8;nt++){
                const int col = warp_n*64 + nt*8 + t4*2;
                float v0 = acc[mt][nt][half*2+0], v1 = acc[mt][nt][half*2+1];
                if (mat==3){
                    v0 = sigmoidf_(v0 + bg[col]);
                    v1 = sigmoidf_(v1 + bg[col+1]);
                }
                *(float2*)(dst + (size_t)row*C_ + col) = make_float2(v0, v1);
            }
        }
    }
}

// ---------------------------------------------------------------------------
// Attention via mma.sync tf32. One CTA per (i,g). 8 warps, 64-key chunks.
// No-max softmax (logits are small: |s| < ~6, exp safe in fp32).
// E computed on QK fragments in registers; per-k sums via shfl + [64][9] table;
// E stored to smem as fp16 (exact in tf32); 1/sum folded into V cooperatively.
// smem: sK[64][36] f32, sV[64][40] f32, sS[64][264] f16, sSum[64][9] f32.
// ---------------------------------------------------------------------------
#define SSH 264                          // halves per sS row
#define SK_OFF 0
#define SV_OFF (64*36)                   // 2304 floats
#define SS_OFF (SV_OFF + 64*40)          // 4864 floats (half* base)
#define SUM_OFF (SS_OFF + (64*SSH)/2)    // 4864 + 8448 = 13312
#define ATTN_SMEM ((SUM_OFF + 64*9)*4)   // 55552 B

__global__ void __launch_bounds__(256,2) attn_kernel()
{
    extern __shared__ float sm[];
    float*  sK   = sm + SK_OFF;              // [64][36]
    float*  sV   = sm + SV_OFF;              // [64][40]
    __half* sS   = (__half*)(sm + SS_OFF);   // [64][SSH] halves, k-major
    float*  sSum = sm + SUM_OFF;             // [64][9]

    const int tid = threadIdx.x, wid = tid>>5, lane = tid&31;
    const int g4 = lane>>2, t4 = lane&3;
    const int bi = blockIdx.x >> 2;
    const int g  = blockIdx.x & 3;
    const int jb = wid * 32;               // warp's j block

    // Q fragments (B operand of S^T mma), register-resident
    uint32_t qb[4][4][2];
    {
        const float* qbase = d_q + (size_t)bi*L_*C_ + g*P_;
        #pragma unroll
        for (int nt=0;nt<4;nt++){
            const float* qr = qbase + (size_t)(jb + nt*8 + g4)*C_;
            #pragma unroll
            for (int ks=0;ks<4;ks++){
                qb[nt][ks][0] = __float_as_uint(f2tf32(qr[ks*8 + t4]));
                qb[nt][ks][1] = __float_as_uint(f2tf32(qr[ks*8 + 4 + t4]));
            }
        }
    }

    float oacc[2][4][4];
    #pragma unroll
    for (int mt=0;mt<2;mt++)
        #pragma unroll
        for (int nt=0;nt<4;nt++)
            #pragma unroll
            for (int e=0;e<4;e++) oacc[mt][nt][e]=0.f;

    const float* biasg = d_bT + (size_t)g*R_;

    for (int kt=0; kt<4; kt++){
        const int k0 = kt*64;
        __syncthreads();   // sK/sV/sS free (prev PV done)
        // stage K (tf32-rounded) and V (raw fp32; rounded after inv fold)
        #pragma unroll
        for (int i=tid; i<512; i+=256){
            int row = i>>3, c4 = i&7;
            size_t ga = (size_t)(bi*L_ + k0 + row)*C_ + g*P_ + c4*4;
            float4 kv = *(const float4*)(d_k + ga);
            float4 vv = *(const float4*)(d_v + ga);
            float* dk = sK + row*36 + c4*4;
            dk[0]=f2tf32(kv.x); dk[1]=f2tf32(kv.y); dk[2]=f2tf32(kv.z); dk[3]=f2tf32(kv.w);
            *(float4*)(sV + row*40 + c4*4) = vv;
        }
        __syncthreads();

        // ---- S^T mma + exp + per-k partial sums, two 32-row halves ----
        #pragma unroll
        for (int h=0; h<2; h++){
            float sacc[2][4][4];
            #pragma unroll
            for (int mt=0;mt<2;mt++)
                #pragma unroll
                for (int nt=0;nt<4;nt++){
                    const float* bp = biasg + (size_t)(k0 + h*32 + mt*16 + g4)*L_ + jb + nt*8 + 2*t4;
                    float2 lo = *(const float2*)bp;
                    float2 hi = *(const float2*)(bp + 8*L_);
                    sacc[mt][nt][0]=lo.x; sacc[mt][nt][1]=lo.y;
                    sacc[mt][nt][2]=hi.x; sacc[mt][nt][3]=hi.y;
                }
            #pragma unroll
            for (int ks=0; ks<4; ks++){
                const int kc = ks*8 + t4;
                uint32_t a[2][4];
                #pragma unroll
                for (int mt=0;mt<2;mt++){
                    const float* pa = sK + (h*32 + mt*16 + g4)*36 + kc;
                    a[mt][0]=__float_as_uint(pa[0]);
                    a[mt][1]=__float_as_uint(pa[8*36]);
                    a[mt][2]=__float_as_uint(pa[4]);
                    a[mt][3]=__float_as_uint(pa[8*36+4]);
                }
                #pragma unroll
                for (int mt=0;mt<2;mt++)
                    #pragma unroll
                    for (int nt=0;nt<4;nt++)
                        mma_tf32(sacc[mt][nt], a[mt], qb[nt][ks]);
            }
            // exp on fragments, fp16 store, per-k partial sums via shfl(t4)
            #pragma unroll
            for (int mt=0;mt<2;mt++){
                const int rA = h*32 + mt*16 + g4;
                float sumA = 0.f, sumB = 0.f;
                #pragma unroll
                for (int nt=0;nt<4;nt++){
                    float e0 = __expf(sacc[mt][nt][0]);
                    float e1 = __expf(sacc[mt][nt][1]);
                    float e2 = __expf(sacc[mt][nt][2]);
                    float e3 = __expf(sacc[mt][nt][3]);
                    sumA += e0 + e1;
                    sumB += e2 + e3;
                    const int col = jb + nt*8 + 2*t4;
                    *(__half2*)(sS + rA*SSH + col)     = __floats2half2_rn(e0, e1);
                    *(__half2*)(sS + (rA+8)*SSH + col) = __floats2half2_rn(e2, e3);
                }
                sumA += __shfl_xor_sync(0xffffffffu, sumA, 1);
                sumA += __shfl_xor_sync(0xffffffffu, sumA, 2);
                sumB += __shfl_xor_sync(0xffffffffu, sumB, 1);
                sumB += __shfl_xor_sync(0xffffffffu, sumB, 2);
                if (t4 == 0){
                    sSum[rA*9 + wid]     = sumA;
                    sSum[(rA+8)*9 + wid] = sumB;
                }
            }
        }
        __syncthreads();

        // ---- fold 1/sum into V cooperatively (each thread: 1 row-quarter) ----
        {
            const int r = tid >> 2, cseg = (tid & 3) * 8;
            float s = 0.f;
            #pragma unroll
            for (int w=0; w<8; w++) s += sSum[r*9 + w];
            const float inv = __frcp_rn(s);
            float* vp = sV + r*40 + cseg;
            #pragma unroll
            for (int c=0; c<8; c++) vp[c] = f2tf32(vp[c]*inv);
        }
        __syncthreads();

        // ---- PV mma: M=warp's 32 j, N=32 c, K=64 k; A = E (fp16, exact) ----
        #pragma unroll
        for (int ks=0; ks<8; ks++){
            const int kk = ks*8 + t4;
            uint32_t a[2][4], b[4][2];
            #pragma unroll
            for (int mt=0;mt<2;mt++){
                const __half* pa = sS + kk*SSH + jb + mt*16 + g4;
                a[mt][0]=__float_as_uint(__half2float(pa[0]));
                a[mt][1]=__float_as_uint(__half2float(pa[8]));
                a[mt][2]=__float_as_uint(__half2float(pa[4*SSH]));
                a[mt][3]=__float_as_uint(__half2float(pa[4*SSH+8]));
            }
            #pragma unroll
            for (int nt=0;nt<4;nt++){
                const float* pb = sV + kk*40 + nt*8 + g4;
                b[nt][0]=__float_as_uint(pb[0]);
                b[nt][1]=__float_as_uint(pb[4*40]);
            }
            #pragma unroll
            for (int mt=0;mt<2;mt++)
                #pragma unroll
                for (int nt=0;nt<4;nt++)
                    mma_tf32(oacc[mt][nt], a[mt], b[nt]);
        }
    }

    // ---- epilogue: gate mul + store ----
    #pragma unroll
    for (int mt=0;mt<2;mt++)
        #pragma unroll
        for (int half=0;half<2;half++){
            const int j = jb + mt*16 + g4 + half*8;
            #pragma unroll
            for (int nt=0;nt<4;nt++){
                const int c = nt*8 + 2*t4;
                size_t ga = (size_t)(bi*L_ + j)*C_ + g*P_ + c;
                float2 gt = *(const float2*)(d_gt + ga);
                float v0 = oacc[mt][nt][half*2+0]*gt.x;
                float v1 = oacc[mt][nt][half*2+1]*gt.y;
                *(float2*)(d_o + ga) = make_float2(v0, v1);
            }
        }
}

// ---------------------------------------------------------------------------
// Out-proj via mma.sync tf32. CTA: 128x128. out = d_o @ Wo + bo
// ---------------------------------------------------------------------------
__global__ void __launch_bounds__(256,2) outproj_kernel(
    const float* __restrict__ bo, float* __restrict__ out)
{
    extern __shared__ float sm[];
    float* sA = sm;
    float* sB = sm + 128*PAD;

    const int tid = threadIdx.x, wid = tid>>5, lane = tid&31;
    const int warp_m = wid & 3, warp_n = wid >> 2;
    const int rbase = blockIdx.x * 128;

    float acc[2][8][4];
    #pragma unroll
    for (int mt=0;mt<2;mt++)
        #pragma unroll
        for (int nt=0;nt<8;nt++)
            #pragma unroll
            for (int e=0;e<4;e++) acc[mt][nt][e]=0.f;

    const int g4 = lane>>2, t4 = lane&3;

    for (int kc=0; kc<2; kc++){
        #pragma unroll 4
        for (int i=tid; i<2048; i+=256){
            int row = i>>4, k4 = i&15;
            float4 v = ((const float4*)d_o)[(size_t)(rbase+row)*32 + kc*16 + k4];
            float* d = sA + row*PAD + k4*4;
            d[0]=f2tf32(v.x); d[1]=f2tf32(v.y); d[2]=f2tf32(v.z); d[3]=f2tf32(v.w);
        }
        #pragma unroll 4
        for (int i=tid; i<2048; i+=256){
            int col = i>>4, k4 = i&15;
            float4 v = ((const float4*)d_WoT)[(size_t)col*32 + kc*16 + k4];
            *(float4*)(sB + col*PAD + k4*4) = v;
        }
        __syncthreads();

        #pragma unroll
        for (int k8=0;k8<8;k8++){
            const int k0 = k8*8;
            uint32_t a[2][4];
            #pragma unroll
            for (int mt=0;mt<2;mt++){
                const float* pa = sA + (warp_m*32 + mt*16 + g4)*PAD + k0 + t4;
                a[mt][0]=__float_as_uint(pa[0]);
                a[mt][1]=__float_as_uint(pa[8*PAD]);
                a[mt][2]=__float_as_uint(pa[4]);
                a[mt][3]=__float_as_uint(pa[8*PAD+4]);
            }
            #pragma unroll
            for (int nt=0;nt<8;nt++){
                const float* pb = sB + (warp_n*64 + nt*8 + g4)*PAD + k0 + t4;
                uint32_t b[2];
                b[0]=__float_as_uint(pb[0]);
                b[1]=__float_as_uint(pb[4]);
                mma_tf32(acc[0][nt], a[0], b);
                mma_tf32(acc[1][nt], a[1], b);
            }
        }
        __syncthreads();
    }

    #pragma unroll
    for (int mt=0;mt<2;mt++){
        #pragma unroll
        for (int half=0;half<2;half++){
            const int row = rbase + warp_m*32 + mt*16 + g4 + half*8;
            #pragma unroll
            for (int nt=0;nt<8;nt++){
                const int col = warp_n*64 + nt*8 + t4*2;
                float v0 = acc[mt][nt][half*2+0] + bo[col];
                float v1 = acc[mt][nt][half*2+1] + bo[col+1];
                *(float2*)(out + (size_t)row*C_ + col) = make_float2(v0, v1);
            }
        }
    }
}

// ---------------------------------------------------------------------------
extern "C" void kernel_launch(void* const* d_in, const int* in_sizes, int n_in,
                              void* d_out, int out_size)
{
    const float* x  = (const float*)d_in[0];
    const float* Wq = (const float*)d_in[1];
    const float* Wk = (const float*)d_in[2];
    const float* Wv = (const float*)d_in[3];
    const float* Wb = (const float*)d_in[4];
    const float* Wg = (const float*)d_in[5];
    const float* bg = (const float*)d_in[6];
    const float* Wo = (const float*)d_in[7];
    const float* bo = (const float*)d_in[8];
    float* out = (float*)d_out;

    cudaFuncSetAttribute(proj_kernel,
                         cudaFuncAttributeMaxDynamicSharedMemorySize, GEMM_SMEM);
    cudaFuncSetAttribute(attn_kernel,
                         cudaFuncAttributeMaxDynamicSharedMemorySize, ATTN_SMEM);
    cudaFuncSetAttribute(outproj_kernel,
                         cudaFuncAttributeMaxDynamicSharedMemorySize, GEMM_SMEM);

    prep_kernel<<<640, 128>>>(Wq, Wk, Wv, Wg, Wo);
    bias_kernel<<<256, 256>>>(x, Wb);
    proj_kernel<<<dim3(R_/128, 4), 256, GEMM_SMEM>>>(x, bg);
    attn_kernel<<<L_*G_, 256, ATTN_SMEM>>>();
    outproj_kernel<<<R_/128, 256, GEMM_SMEM>>>(bo, out);
}

// round 10
// speedup vs baseline: 1.3127x; 1.3127x over previous
#include <cuda_runtime.h>
#include <math.h>
#include <stdint.h>
#include <cuda_fp16.h>

#define L_ 256
#define C_ 128
#define G_ 4
#define P_ 32
#define R_ (L_*L_)   // 65536 rows

// Scratch (allocation-free device globals, 16B-aligned for vector access)
static __device__ __align__(16) __half d_qh [R_*C_];
static __device__ __align__(16) __half d_kh [R_*C_];
static __device__ __align__(16) __half d_vTh[R_*C_];   // [g][c][i][k]
static __device__ __align__(16) __half d_gth[R_*C_];
static __device__ __align__(16) __half d_oh [R_*C_];
static __device__ __align__(16) __half d_bTh[(size_t)G_*R_];  // [g][k][j]
static __device__ __align__(16) __half d_WTh [512*128];  // fused [Wq*qs|Wk|Wv|Wg]^T [n][k]
static __device__ __align__(16) __half d_WoTh[128*128];  // Wo^T [n][k]

__device__ __forceinline__ float sigmoidf_(float x){ return 1.f/(1.f+__expf(-x)); }

__device__ __forceinline__ void mma_f16(float* d, const uint32_t* a, const uint32_t* b){
    asm volatile("mma.sync.aligned.m16n8k16.row.col.f32.f16.f16.f32 "
        "{%0,%1,%2,%3}, {%4,%5,%6,%7}, {%8,%9}, {%0,%1,%2,%3};"
        : "+f"(d[0]),"+f"(d[1]),"+f"(d[2]),"+f"(d[3])
        : "r"(a[0]),"r"(a[1]),"r"(a[2]),"r"(a[3]), "r"(b[0]),"r"(b[1]));
}

// ---------------------------------------------------------------------------
// Prep: W^T fp16 [n][k]; fold 1/sqrt(P) into WqT.
// ---------------------------------------------------------------------------
__global__ void prep_kernel(const float* __restrict__ Wq, const float* __restrict__ Wk,
                            const float* __restrict__ Wv, const float* __restrict__ Wg,
                            const float* __restrict__ Wo)
{
    int n = blockIdx.x, k = threadIdx.x;
    if (n < 512){
        int m = n>>7, c = n&127;
        const float* W = (m==0)?Wq:(m==1)?Wk:(m==2)?Wv:Wg;
        float w = W[k*C_ + c];
        if (m==0) w *= 0.17677669529663687f;   // 1/sqrt(32)
        d_WTh[n*C_ + k] = __float2half(w);
    } else {
        int c = n - 512;
        d_WoTh[c*C_ + k] = __float2half(Wo[k*C_ + c]);
    }
}

// ---------------------------------------------------------------------------
// Bias: d_bTh[g][k][j] = x[j*L+k,:] . Wb[:,g]  (fp32 math, fp16 store)
// ---------------------------------------------------------------------------
__global__ void __launch_bounds__(256) bias_kernel(const float* __restrict__ x,
                                                   const float* __restrict__ Wb)
{
    __shared__ float4 sWb[128];
    int tid = threadIdx.x;
    if (tid < 128)
        sWb[tid] = make_float4(Wb[tid*4+0], Wb[tid*4+1], Wb[tid*4+2], Wb[tid*4+3]);
    __syncthreads();
    int r = blockIdx.x*256 + tid;
    const float4* xr = (const float4*)(x + (size_t)r*C_);
    float a0=0.f,a1=0.f,a2=0.f,a3=0.f;
    #pragma unroll 8
    for (int c4=0;c4<32;c4++){
        float4 xv = xr[c4];
        float4 w0 = sWb[c4*4+0], w1 = sWb[c4*4+1], w2 = sWb[c4*4+2], w3 = sWb[c4*4+3];
        a0 = fmaf(xv.x,w0.x,a0); a1 = fmaf(xv.x,w0.y,a1); a2 = fmaf(xv.x,w0.z,a2); a3 = fmaf(xv.x,w0.w,a3);
        a0 = fmaf(xv.y,w1.x,a0); a1 = fmaf(xv.y,w1.y,a1); a2 = fmaf(xv.y,w1.z,a2); a3 = fmaf(xv.y,w1.w,a3);
        a0 = fmaf(xv.z,w2.x,a0); a1 = fmaf(xv.z,w2.y,a1); a2 = fmaf(xv.z,w2.z,a2); a3 = fmaf(xv.z,w2.w,a3);
        a0 = fmaf(xv.w,w3.x,a0); a1 = fmaf(xv.w,w3.y,a1); a2 = fmaf(xv.w,w3.z,a2); a3 = fmaf(xv.w,w3.w,a3);
    }
    int kk = r & (L_-1), jj = r >> 8;
    d_bTh[(size_t)0*R_ + kk*L_ + jj] = __float2half(a0);
    d_bTh[(size_t)1*R_ + kk*L_ + jj] = __float2half(a1);
    d_bTh[(size_t)2*R_ + kk*L_ + jj] = __float2half(a2);
    d_bTh[(size_t)3*R_ + kk*L_ + jj] = __float2half(a3);
}

// ---------------------------------------------------------------------------
// Proj via mma m16n8k16 fp16. CTA: 128 rows x 128 cols, full K=128 staged.
// Grid (512, 4): by = matrix (0:q 1:k 2:v 3:gate). V written transposed.
// smem rows: 136 halves (68 words): banks 4r+t4 conflict-free.
// ---------------------------------------------------------------------------
#define PADH 136
#define GEMM_SMEM (2*128*PADH*2)   // 69632 B

__global__ void __launch_bounds__(256,2) proj_kernel(
    const float* __restrict__ x, const float* __restrict__ bg)
{
    extern __shared__ __half smh[];
    __half* sA = smh;                // [128][136]
    __half* sB = smh + 128*PADH;     // [128][136]

    const int tid = threadIdx.x, wid = tid>>5, lane = tid&31;
    const int warp_m = wid & 3, warp_n = wid >> 2;
    const int g4 = lane>>2, t4 = lane&3;
    const int rbase = blockIdx.x * 128;
    const int mat   = blockIdx.y;
    const int cbase = mat * 128;

    // stage A: x fp32 -> fp16
    #pragma unroll 4
    for (int i=tid; i<4096; i+=256){
        int row = i>>5, k4 = i&31;
        float4 v = ((const float4*)x)[(size_t)(rbase+row)*32 + k4];
        __half2* d = (__half2*)sA + row*(PADH/2) + k4*2;
        d[0] = __floats2half2_rn(v.x, v.y);
        d[1] = __floats2half2_rn(v.z, v.w);
    }
    // stage B: d_WTh copy
    #pragma unroll 4
    for (int i=tid; i<2048; i+=256){
        int row = i>>4, seg = i&15;
        ((uint4*)sB)[row*17 + seg] = ((const uint4*)d_WTh)[(size_t)(cbase+row)*16 + seg];
    }
    __syncthreads();

    float acc[2][8][4];
    #pragma unroll
    for (int mt=0;mt<2;mt++)
        #pragma unroll
        for (int nt=0;nt<8;nt++)
            #pragma unroll
            for (int e=0;e<4;e++) acc[mt][nt][e]=0.f;

    const uint32_t* sAw = (const uint32_t*)sA;
    const uint32_t* sBw = (const uint32_t*)sB;

    #pragma unroll
    for (int ks=0; ks<8; ks++){
        uint32_t a[2][4];
        #pragma unroll
        for (int mt=0;mt<2;mt++){
            int w = (warp_m*32 + mt*16 + g4)*(PADH/2) + ks*8 + t4;
            a[mt][0]=sAw[w]; a[mt][1]=sAw[w+8*(PADH/2)];
            a[mt][2]=sAw[w+4]; a[mt][3]=sAw[w+8*(PADH/2)+4];
        }
        #pragma unroll
        for (int nt=0;nt<8;nt++){
            int w = (warp_n*64 + nt*8 + g4)*(PADH/2) + ks*8 + t4;
            uint32_t b[2] = { sBw[w], sBw[w+4] };
            mma_f16(acc[0][nt], a[0], b);
            mma_f16(acc[1][nt], a[1], b);
        }
    }

    // epilogue
    #pragma unroll
    for (int mt=0;mt<2;mt++){
        #pragma unroll
        for (int half=0;half<2;half++){
            const int row = rbase + warp_m*32 + mt*16 + g4 + half*8;
            #pragma unroll
            for (int nt=0;nt<8;nt++){
                const int col = warp_n*64 + nt*8 + t4*2;   // mat-local 0..127
                float v0 = acc[mt][nt][half*2+0], v1 = acc[mt][nt][half*2+1];
                if (mat==0){
                    *(__half2*)(d_qh + (size_t)row*C_ + col) = __floats2half2_rn(v0,v1);
                } else if (mat==1){
                    *(__half2*)(d_kh + (size_t)row*C_ + col) = __floats2half2_rn(v0,v1);
                } else if (mat==3){
                    v0 = sigmoidf_(v0 + bg[col]); v1 = sigmoidf_(v1 + bg[col+1]);
                    *(__half2*)(d_gth + (size_t)row*C_ + col) = __floats2half2_rn(v0,v1);
                } else {
                    // V transposed: d_vTh[((g*32+c)*256 + i)*256 + k]
                    int g = col>>5, c = col&31;
                    int ii = row>>8, kk = row&255;
                    d_vTh[((size_t)(g*32+c  )*256 + ii)*256 + kk] = __float2half(v0);
                    d_vTh[((size_t)(g*32+c+1)*256 + ii)*256 + kk] = __float2half(v1);
                }
            }
        }
    }
}

// ---------------------------------------------------------------------------
// Attention, full fp16 mma. One CTA per (i,g). 8 warps, 64-key chunks.
// No-max softmax. sK[64][40]h, sVT[32][72]h (transposed V), sST[256][72]h
// ([j][k] E for PV A), sSum[64][9] f32.
// ---------------------------------------------------------------------------
#define SKH  0
#define SVTH (64*40)                 // 2560
#define SSTH (SVTH + 32*72)          // 4864
#define SUMH (SSTH + 256*72)         // 23296 (halves)
#define ATTN_SMEM (SUMH*2 + 64*9*4)  // 46592 + 2304 = 48896 B

__global__ void __launch_bounds__(256,2) attn_kernel()
{
    extern __shared__ __half smh[];
    __half* sK   = smh + SKH;
    __half* sVT  = smh + SVTH;
    __half* sST  = smh + SSTH;
    float*  sSum = (float*)(smh + SUMH);

    const int tid = threadIdx.x, wid = tid>>5, lane = tid&31;
    const int g4 = lane>>2, t4 = lane&3;
    const int bi = blockIdx.x >> 2;
    const int g  = blockIdx.x & 3;
    const int jb = wid * 32;

    // Q fragments from global fp16 (B operand of QK mma)
    uint32_t qb[4][2][2];
    {
        #pragma unroll
        for (int nt=0;nt<4;nt++){
            const uint32_t* qw = (const uint32_t*)d_qh
                + (size_t)(bi*L_ + jb + nt*8 + g4)*(C_/2) + g*16;
            qb[nt][0][0] = qw[t4];      qb[nt][0][1] = qw[t4+4];
            qb[nt][1][0] = qw[t4+8];    qb[nt][1][1] = qw[t4+12];
        }
    }

    float oacc[2][4][4];
    #pragma unroll
    for (int mt=0;mt<2;mt++)
        #pragma unroll
        for (int nt=0;nt<4;nt++)
            #pragma unroll
            for (int e=0;e<4;e++) oacc[mt][nt][e]=0.f;

    const __half* biasg = d_bTh + (size_t)g*R_;

    for (int kt=0; kt<4; kt++){
        const int k0 = kt*64;
        __syncthreads();
        {   // stage K [64][32] (uint4 copy)
            int row = tid>>2, seg = tid&3;
            ((uint4*)sK)[row*5 + seg] =
                ((const uint4*)d_kh)[(size_t)(bi*L_ + k0 + row)*16 + g*4 + seg];
            // stage V^T [32][64] (uint4 copy from d_vTh)
            int c = tid>>3, s2 = tid&7;
            ((uint4*)sVT)[c*9 + s2] =
                ((const uint4*)d_vTh)[((size_t)(g*32+c)*256 + bi)*32 + kt*8 + s2];
        }
        __syncthreads();

        // ---- QK: S^T[k][j] via fp16 mma; exp on fragments; [j][k] store ----
        const uint32_t* sKw = (const uint32_t*)sK;
        #pragma unroll
        for (int h=0; h<2; h++){
            float sacc[2][4][4];
            #pragma unroll
            for (int mt=0;mt<2;mt++)
                #pragma unroll
                for (int nt=0;nt<4;nt++){
                    const __half* bp = biasg + (size_t)(k0 + h*32 + mt*16 + g4)*L_ + jb + nt*8 + 2*t4;
                    float2 lo = __half22float2(*(const __half2*)bp);
                    float2 hi = __half22float2(*(const __half2*)(bp + 8*L_));
                    sacc[mt][nt][0]=lo.x; sacc[mt][nt][1]=lo.y;
                    sacc[mt][nt][2]=hi.x; sacc[mt][nt][3]=hi.y;
                }
            #pragma unroll
            for (int ks=0; ks<2; ks++){
                uint32_t a[2][4];
                #pragma unroll
                for (int mt=0;mt<2;mt++){
                    int w = (h*32 + mt*16 + g4)*20 + ks*8 + t4;
                    a[mt][0]=sKw[w]; a[mt][1]=sKw[w+8*20];
                    a[mt][2]=sKw[w+4]; a[mt][3]=sKw[w+8*20+4];
                }
                #pragma unroll
                for (int mt=0;mt<2;mt++)
                    #pragma unroll
                    for (int nt=0;nt<4;nt++)
                        mma_f16(sacc[mt][nt], a[mt], qb[nt][ks]);
            }
            // exp, transposed store [j][k], per-k partial sums
            #pragma unroll
            for (int mt=0;mt<2;mt++){
                const int rA = h*32 + mt*16 + g4;
                float sumA = 0.f, sumB = 0.f;
                #pragma unroll
                for (int nt=0;nt<4;nt++){
                    const int col = jb + nt*8 + 2*t4;
                    float e0 = __expf(sacc[mt][nt][0]);
                    float e1 = __expf(sacc[mt][nt][1]);
                    float e2 = __expf(sacc[mt][nt][2]);
                    float e3 = __expf(sacc[mt][nt][3]);
                    sumA += e0 + e1;
                    sumB += e2 + e3;
                    sST[(col  )*72 + rA    ] = __float2half(e0);
                    sST[(col+1)*72 + rA    ] = __float2half(e1);
                    sST[(col  )*72 + rA + 8] = __float2half(e2);
                    sST[(col+1)*72 + rA + 8] = __float2half(e3);
                }
                sumA += __shfl_xor_sync(0xffffffffu, sumA, 1);
                sumA += __shfl_xor_sync(0xffffffffu, sumA, 2);
                sumB += __shfl_xor_sync(0xffffffffu, sumB, 1);
                sumB += __shfl_xor_sync(0xffffffffu, sumB, 2);
                if (t4 == 0){
                    sSum[rA*9 + wid]     = sumA;
                    sSum[(rA+8)*9 + wid] = sumB;
                }
            }
        }
        __syncthreads();

        // ---- fold 1/sum into V^T: thread handles k=tid&63, 8 c's ----
        {
            const int k = tid & 63, cq = (tid >> 6) * 8;
            float s = 0.f;
            #pragma unroll
            for (int w=0; w<8; w++) s += sSum[k*9 + w];
            const float inv = __frcp_rn(s);
            #pragma unroll
            for (int c=0; c<8; c++){
                __half* vp = sVT + (cq+c)*72 + k;
                *vp = __float2half(__half2float(*vp) * inv);
            }
        }
        __syncthreads();

        // ---- PV: O[j][c] += E[j][k] * V^T[c][k], fp16 mma, K=64 ----
        const uint32_t* sSw = (const uint32_t*)sST;
        const uint32_t* sVw = (const uint32_t*)sVT;
        #pragma unroll
        for (int ks=0; ks<4; ks++){
            uint32_t a[2][4], b[4][2];
            #pragma unroll
            for (int mt=0;mt<2;mt++){
                int w = (jb + mt*16 + g4)*36 + ks*8 + t4;
                a[mt][0]=sSw[w]; a[mt][1]=sSw[w+8*36];
                a[mt][2]=sSw[w+4]; a[mt][3]=sSw[w+8*36+4];
            }
            #pragma unroll
            for (int nt=0;nt<4;nt++){
                int w = (nt*8 + g4)*36 + ks*8 + t4;
                b[nt][0]=sVw[w]; b[nt][1]=sVw[w+4];
            }
            #pragma unroll
            for (int mt=0;mt<2;mt++)
                #pragma unroll
                for (int nt=0;nt<4;nt++)
                    mma_f16(oacc[mt][nt], a[mt], b[nt]);
        }
    }

    // ---- epilogue: gate (fp16) mul + fp16 store ----
    #pragma unroll
    for (int mt=0;mt<2;mt++)
        #pragma unroll
        for (int half=0;half<2;half++){
            const int j = jb + mt*16 + g4 + half*8;
            #pragma unroll
            for (int nt=0;nt<4;nt++){
                const int c = nt*8 + 2*t4;
                size_t ga = (size_t)(bi*L_ + j)*C_ + g*P_ + c;
                float2 gt = __half22float2(*(const __half2*)(d_gth + ga));
                float v0 = oacc[mt][nt][half*2+0]*gt.x;
                float v1 = oacc[mt][nt][half*2+1]*gt.y;
                *(__half2*)(d_oh + ga) = __floats2half2_rn(v0, v1);
            }
        }
}

// ---------------------------------------------------------------------------
// Out-proj fp16 mma: out = d_oh @ Wo + bo (fp32 out)
// ---------------------------------------------------------------------------
__global__ void __launch_bounds__(256,2) outproj_kernel(
    const float* __restrict__ bo, float* __restrict__ out)
{
    extern __shared__ __half smh[];
    __half* sA = smh;
    __half* sB = smh + 128*PADH;

    const int tid = threadIdx.x, wid = tid>>5, lane = tid&31;
    const int warp_m = wid & 3, warp_n = wid >> 2;
    const int g4 = lane>>2, t4 = lane&3;
    const int rbase = blockIdx.x * 128;

    #pragma unroll 4
    for (int i=tid; i<2048; i+=256){
        int row = i>>4, seg = i&15;
        ((uint4*)sA)[row*17 + seg] = ((const uint4*)d_oh)[(size_t)(rbase+row)*16 + seg];
        ((uint4*)sB)[row*17 + seg] = ((const uint4*)d_WoTh)[(size_t)row*16 + seg];
    }
    __syncthreads();

    float acc[2][8][4];
    #pragma unroll
    for (int mt=0;mt<2;mt++)
        #pragma unroll
        for (int nt=0;nt<8;nt++)
            #pragma unroll
            for (int e=0;e<4;e++) acc[mt][nt][e]=0.f;

    const uint32_t* sAw = (const uint32_t*)sA;
    const uint32_t* sBw = (const uint32_t*)sB;

    #pragma unroll
    for (int ks=0; ks<8; ks++){
        uint32_t a[2][4];
        #pragma unroll
        for (int mt=0;mt<2;mt++){
            int w = (warp_m*32 + mt*16 + g4)*(PADH/2) + ks*8 + t4;
            a[mt][0]=sAw[w]; a[mt][1]=sAw[w+8*(PADH/2)];
            a[mt][2]=sAw[w+4]; a[mt][3]=sAw[w+8*(PADH/2)+4];
        }
        #pragma unroll
        for (int nt=0;nt<8;nt++){
            int w = (warp_n*64 + nt*8 + g4)*(PADH/2) + ks*8 + t4;
            uint32_t b[2] = { sBw[w], sBw[w+4] };
            mma_f16(acc[0][nt], a[0], b);
            mma_f16(acc[1][nt], a[1], b);
        }
    }

    #pragma unroll
    for (int mt=0;mt<2;mt++){
        #pragma unroll
        for (int half=0;half<2;half++){
            const int row = rbase + warp_m*32 + mt*16 + g4 + half*8;
            #pragma unroll
            for (int nt=0;nt<8;nt++){
                const int col = warp_n*64 + nt*8 + t4*2;
                float v0 = acc[mt][nt][half*2+0] + bo[col];
                float v1 = acc[mt][nt][half*2+1] + bo[col+1];
                *(float2*)(out + (size_t)row*C_ + col) = make_float2(v0, v1);
            }
        }
    }
}

// ---------------------------------------------------------------------------
extern "C" void kernel_launch(void* const* d_in, const int* in_sizes, int n_in,
                              void* d_out, int out_size)
{
    const float* x  = (const float*)d_in[0];
    const float* Wq = (const float*)d_in[1];
    const float* Wk = (const float*)d_in[2];
    const float* Wv = (const float*)d_in[3];
    const float* Wb = (const float*)d_in[4];
    const float* Wg = (const float*)d_in[5];
    const float* bg = (const float*)d_in[6];
    const float* Wo = (const float*)d_in[7];
    const float* bo = (const float*)d_in[8];
    float* out = (float*)d_out;

    cudaFuncSetAttribute(proj_kernel,
                         cudaFuncAttributeMaxDynamicSharedMemorySize, GEMM_SMEM);
    cudaFuncSetAttribute(attn_kernel,
                         cudaFuncAttributeMaxDynamicSharedMemorySize, ATTN_SMEM);
    cudaFuncSetAttribute(outproj_kernel,
                         cudaFuncAttributeMaxDynamicSharedMemorySize, GEMM_SMEM);

    prep_kernel<<<640, 128>>>(Wq, Wk, Wv, Wg, Wo);
    bias_kernel<<<256, 256>>>(x, Wb);
    proj_kernel<<<dim3(R_/128, 4), 256, GEMM_SMEM>>>(x, bg);
    attn_kernel<<<L_*G_, 256, ATTN_SMEM>>>();
    outproj_kernel<<<R_/128, 256, GEMM_SMEM>>>(bo, out);
}